// round 10
// baseline (speedup 1.0000x reference)
#include <cuda_runtime.h>

#define BB 1024
#define TT 128
#define KK 128
#define START_TAG 126
#define STOP_TAG 127
#define NREC 132               // record slots per buffer: 0..130 data/pads, 131 dump
#define DUMP_SLOT 131
#define CLRX 0xFF7FFFFFu       // -FLT_MAX bits

// Per-warp length from the monotone mask row. Mask dtype detected from first word.
__device__ __forceinline__ int warp_len(const void* masks, int b, int lane) {
    unsigned w0 = *(const unsigned*)masks;
    int cnt;
    if (w0 == 0x01010101u) {
        unsigned v = ((const unsigned*)((const char*)masks + (size_t)b * TT))[lane];
        cnt = __popc(v & 0x01010101u);
    } else if (w0 == 0x3F800000u) {
        float4 v = ((const float4*)((const float*)masks + (size_t)b * TT))[lane];
        cnt = (v.x != 0.0f) + (v.y != 0.0f) + (v.z != 0.0f) + (v.w != 0.0f);
    } else {
        int4 v = ((const int4*)((const int*)masks + (size_t)b * TT))[lane];
        cnt = (v.x != 0) + (v.y != 0) + (v.z != 0) + (v.w != 0);
    }
    return __reduce_add_sync(0xffffffffu, cnt);
}

// pack (value lower-bound bits | index) for lagged-max pipeline; x+64 > 0 always
__device__ __forceinline__ unsigned pack4(float a0, float a1, float a2, float a3, int p0) {
    float m01 = fmaxf(a0, a1); int i01 = (a0 >= a1) ? 0 : 1;
    float m23 = fmaxf(a2, a3); int i23 = (a2 >= a3) ? 2 : 3;
    float lm  = fmaxf(m01, m23); int idx = (m01 >= m23) ? i01 : i23;
    return (__float_as_uint(lm + 64.0f) & ~127u) | (unsigned)(p0 + idx);
}

// ---------------------------------------------------------------------------
// Fused Viterbi: warp per batch, lane owns cur/prev = {4*lane .. 4*lane+3}.
// NO warp-collectives on the recurrence cycle: threshold comes from a 1-step
// lagged packed-REDUX bound (max(v_t) >= vhat(v_{t-1}) + T[ph,ch] + fhat(f_t)),
// slot assignment via per-warp SMEM atomicAdd, pads pre-cleared a step early.
// SMEM: 64KB trans + 8x16KB bp + 8x2176B staging ~ 214KB -> 1 CTA/SM.
// ---------------------------------------------------------------------------
extern "C" __global__ void __launch_bounds__(256, 1)
viterbi_kernel(const float* __restrict__ feats,
               const float* __restrict__ trans,
               const void*  __restrict__ masks,
               float* __restrict__ out_score,
               float* __restrict__ out_dec) {
    extern __shared__ char smem[];
    float* ts = (float*)smem;                      // [prev*128 + cur], 64 KB
    __shared__ float s_wr[4];
    __shared__ float s_delta;

    int tid = threadIdx.x;
    int w = tid >> 5, lane = tid & 31;

    uint2*    cand    = (uint2*)(smem + 65536 + 8 * TT * KK + w * 2176);  // 2 x 132 recs
    unsigned* cntp    = (unsigned*)((char*)cand + 2 * NREC * 8);          // 2 counters

    for (int i = tid; i < KK * KK / 4; i += 256)
        ((float4*)ts)[i] = ((const float4*)trans)[i];
    // staging init: clear buf1 slots (used at t=1) + zero counters
    cand[NREC + lane] = make_uint2(CLRX, 0);
    if (lane == 0) { cntp[0] = 0; cntp[1] = 0; }
    __syncthreads();

    // Exact prune bound: Delta = max over cur of (max-min of trans[:,cur]) + margin
    if (tid < 128) {
        float mx = -3.4e38f, mn = 3.4e38f;
        #pragma unroll 8
        for (int p = 0; p < 128; p++) {
            float v = ts[p * 128 + tid];
            mx = fmaxf(mx, v); mn = fminf(mn, v);
        }
        float r = mx - mn;
        #pragma unroll
        for (int o = 16; o; o >>= 1) r = fmaxf(r, __shfl_xor_sync(0xffffffffu, r, o));
        if ((tid & 31) == 0) s_wr[tid >> 5] = r;
    }
    __syncthreads();
    if (tid == 0)
        s_delta = fmaxf(fmaxf(s_wr[0], s_wr[1]), fmaxf(s_wr[2], s_wr[3])) + 1e-3f;
    __syncthreads();
    float delta = s_delta;

    int b = blockIdx.x * 8 + w;
    unsigned char* bp = (unsigned char*)(smem + 65536 + w * (TT * KK));   // 16 KB/warp
    const float4* ts4 = (const float4*)ts;
    int last = warp_len(masks, b, lane) - 1;       // last >= 63

    const float4* fb4 = (const float4*)(feats + (size_t)b * TT * KK);  // 32 float4/row
    int p0 = lane * 4;

    // t = 0: partition = feats[:,0,:] + trans[START,:]
    float4 f0  = fb4[lane];
    float4 tr0 = ((const float4*)(ts + START_TAG * KK))[lane];
    float v0 = f0.x + tr0.x, v1 = f0.y + tr0.y, v2 = f0.z + tr0.z, v3 = f0.w + tr0.w;
    float sv0 = v0, sv1 = v1, sv2 = v2, sv3 = v3;  // snapshot at t == last

    // feat register ring, depth 4
    float4 r0 = fb4[1 * 32 + lane], r1 = fb4[2 * 32 + lane];
    float4 r2 = fb4[3 * 32 + lane], r3 = fb4[4 * 32 + lane];

    // lagged-max pipeline: muv = packed max of v_{t-1}; muf = packed max of f_t
    unsigned muv = __reduce_max_sync(0xffffffffu, pack4(v0, v1, v2, v3, p0));
    unsigned muf = __reduce_max_sync(0xffffffffu, pack4(r0.x, r0.y, r0.z, r0.w, p0));
    // thr for step 1 (prunes v0): vhat_low(v0) - delta   (stalls once on muv)
    float thr = (__uint_as_float(muv & ~127u) - 64.0f) - delta;

    // one Viterbi step; no warp-collectives on the v->v cycle except syncwarp
    auto step = [&](int t, float4 fc, float4 fnext) {
        // flags + slot reservation (single per-warp atomic; deterministic on replay)
        bool g0 = v0 >= thr, g1 = v1 >= thr, g2 = v2 >= thr, g3 = v3 >= thr;
        int k = (int)g0 + (int)g1 + (int)g2 + (int)g3;
        unsigned base = atomicAdd(&cntp[t & 1], (unsigned)k);
        int e1 = (int)base + (int)g0, e2 = e1 + (int)g1, e3 = e2 + (int)g2;
        uint2* cb = cand + ((t & 1) ? NREC : 0);
        uint2* ob = cand + ((t & 1) ? 0 : NREC);
        cb[g0 ? (int)base : DUMP_SLOT] = make_uint2(__float_as_uint(v0), p0 + 0);
        cb[g1 ? e1        : DUMP_SLOT] = make_uint2(__float_as_uint(v1), p0 + 1);
        cb[g2 ? e2        : DUMP_SLOT] = make_uint2(__float_as_uint(v2), p0 + 2);
        cb[g3 ? e3        : DUMP_SLOT] = make_uint2(__float_as_uint(v3), p0 + 3);
        ob[lane] = make_uint2(CLRX, 0);            // pre-clear other buffer (32 slots)
        if (lane == 0) cntp[(t + 1) & 1] = 0;      // reset other counter
        __syncwarp();
        int ncand = (int)cntp[t & 1];              // broadcast LDS, parallel w/ records

        // fast path: records 0-7 (slots >= ncand hold -FLT_MAX from pre-clear)
        const uint4* cb4 = (const uint4*)cb;
        uint4 ra = cb4[0], rb = cb4[1], rc = cb4[2], rd = cb4[3];
        float q0[8], q1[8], q2[8], q3[8]; int pi[8];
        #define LOADREC(K, PVU, PREV)                                                \
        {   float pv = __uint_as_float(PVU); int prev = (int)(PREV); pi[K] = prev;   \
            float4 tr = ts4[prev * 32 + lane];                                       \
            q0[K] = (pv + tr.x) + fc.x; q1[K] = (pv + tr.y) + fc.y;                  \
            q2[K] = (pv + tr.z) + fc.z; q3[K] = (pv + tr.w) + fc.w;                  \
        }
        LOADREC(0, ra.x, ra.y) LOADREC(1, ra.z, ra.w)
        LOADREC(2, rb.x, rb.y) LOADREC(3, rb.z, rb.w)
        LOADREC(4, rc.x, rc.y) LOADREC(5, rc.z, rc.w)
        LOADREC(6, rd.x, rd.y) LOADREC(7, rd.z, rd.w)
        #undef LOADREC

        float b0, b1, b2, b3; int i0, i1, i2, i3;
        #define TREE(Q, BO, IO)                                                      \
        {   bool c01 = Q[0] >= Q[1], c23 = Q[2] >= Q[3];                             \
            bool c45 = Q[4] >= Q[5], c67 = Q[6] >= Q[7];                             \
            float m01 = c01 ? Q[0] : Q[1]; int j01 = c01 ? pi[0] : pi[1];            \
            float m23 = c23 ? Q[2] : Q[3]; int j23 = c23 ? pi[2] : pi[3];            \
            float m45 = c45 ? Q[4] : Q[5]; int j45 = c45 ? pi[4] : pi[5];            \
            float m67 = c67 ? Q[6] : Q[7]; int j67 = c67 ? pi[6] : pi[7];            \
            bool ca = m01 >= m23, cbx = m45 >= m67;                                  \
            float ma = ca ? m01 : m23; int ja = ca ? j01 : j23;                      \
            float mb = cbx ? m45 : m67; int jb = cbx ? j45 : j67;                    \
            bool cf = ma >= mb;                                                      \
            BO = cf ? ma : mb; IO = cf ? ja : jb;                                    \
        }
        TREE(q0, b0, i0) TREE(q1, b1, i1) TREE(q2, b2, i2) TREE(q3, b3, i3)
        #undef TREE

        if (ncand > 8) {                            // warp-uniform, uncommon
            if (ncand > 29) {                       // pads beyond pre-cleared region
                if (lane < 3) cb[ncand + lane] = make_uint2(CLRX, 0);
                __syncwarp();
            }
            int ng = (ncand + 3) >> 2;
            for (int g = 2; g < ng; g++) {
                uint4 rx = cb4[2 * g], ry = cb4[2 * g + 1];
                #define PROC(PVU, PREV)                                                  \
                {   float pv = __uint_as_float(PVU); int prev = (int)(PREV);             \
                    float4 tr = ts4[prev * 32 + lane];                                   \
                    float qa = (pv + tr.x) + fc.x; if (qa > b0) { b0 = qa; i0 = prev; }  \
                    float qb = (pv + tr.y) + fc.y; if (qb > b1) { b1 = qb; i1 = prev; }  \
                    float qc = (pv + tr.z) + fc.z; if (qc > b2) { b2 = qc; i2 = prev; }  \
                    float qd = (pv + tr.w) + fc.w; if (qd > b3) { b3 = qd; i3 = prev; }  \
                }
                PROC(rx.x, rx.y) PROC(rx.z, rx.w) PROC(ry.x, ry.y) PROC(ry.z, ry.w)
                #undef PROC
            }
        }

        // packed backpointers: byte for cur=c at bp[t*128 + c]
        ((unsigned*)(bp + t * KK))[lane] =
            (unsigned)i0 | ((unsigned)i1 << 8) | ((unsigned)i2 << 16) | ((unsigned)i3 << 24);

        v0 = b0; v1 = b1; v2 = b2; v3 = b3;
        bool atlast = (t == last);                  // predicated snapshot (off-chain)
        sv0 = atlast ? v0 : sv0; sv1 = atlast ? v1 : sv1;
        sv2 = atlast ? v2 : sv2; sv3 = atlast ? v3 : sv3;

        // lagged-threshold pipeline (all off the v->v cycle):
        // thr_{t+1} = vhat_low(v_{t-1}) + T[ph, ch(f_t)] + fhat_low(f_t) - delta
        {
            int   ph   = (int)(muv & 127u);
            float vlow = __uint_as_float(muv & ~127u) - 64.0f;
            int   ch   = (int)(muf & 127u);
            float flow = __uint_as_float(muf & ~127u) - 64.0f;
            thr = vlow + ((ts[ph * KK + ch] + flow) - delta);
        }
        muf = __reduce_max_sync(0xffffffffu, pack4(fnext.x, fnext.y, fnext.z, fnext.w, p0));
        muv = __reduce_max_sync(0xffffffffu, pack4(v0, v1, v2, v3, p0));
    };

    #pragma unroll 1
    for (int tb = 1; tb <= 121; tb += 4) {
        int a4 = min(tb + 4, 127) * 32 + lane, a5 = min(tb + 5, 127) * 32 + lane;
        int a6 = min(tb + 6, 127) * 32 + lane, a7 = min(tb + 7, 127) * 32 + lane;
        float4 fa = r0;  r0 = fb4[a4]; step(tb + 0, fa, r1);
        float4 fb_ = r1; r1 = fb4[a5]; step(tb + 1, fb_, r2);
        float4 fcx = r2; r2 = fb4[a6]; step(tb + 2, fcx, r3);
        float4 fd = r3;  r3 = fb4[a7]; step(tb + 3, fd, r0);
    }
    step(125, r0, r1); step(126, r1, r2); step(127, r2, r3);   // t = 1..127 total

    // STOP transition argmax from snapshot (first-index ties)
    float q0 = sv0 + ts[(p0 + 0) * KK + STOP_TAG];
    float q1 = sv1 + ts[(p0 + 1) * KK + STOP_TAG];
    float q2 = sv2 + ts[(p0 + 2) * KK + STOP_TAG];
    float q3 = sv3 + ts[(p0 + 3) * KK + STOP_TAG];
    float bv = q0; int bi = p0;
    if (q1 > bv) { bv = q1; bi = p0 + 1; }
    if (q2 > bv) { bv = q2; bi = p0 + 2; }
    if (q3 > bv) { bv = q3; bi = p0 + 3; }
    #pragma unroll
    for (int o = 16; o; o >>= 1) {
        float ov = __shfl_xor_sync(0xffffffffu, bv, o);
        int   oi = __shfl_xor_sync(0xffffffffu, bi, o);
        if (ov > bv || (ov == bv && oi < bi)) { bv = ov; bi = oi; }
    }
    int cur = bi;   // warp-uniform

    if (out_score && lane == 0) out_score[b] = bv;

    if (out_dec) {
        float* od = out_dec + (size_t)b * TT;
        for (int t = last + 1 + lane; t < TT - 1; t += 32) od[t] = 0.0f;   // masked tail
        if (lane == 0) { od[TT - 1] = (float)cur; od[last] = (float)cur; } // ref quirk
        for (int t = last; t >= 1; t--) {
            cur = bp[t * KK + cur];                 // uniform SMEM pointer chase
            if (lane == 0) od[t - 1] = (float)cur;
        }
    }
}

// ---------------------------------------------------------------------------
extern "C" void kernel_launch(void* const* d_in, const int* in_sizes, int n_in,
                              void* d_out, int out_size) {
    const float* feats = nullptr;
    const float* trans = nullptr;
    const void*  masks = nullptr;
    for (int i = 0; i < n_in; i++) {
        if      (in_sizes[i] == BB * TT * KK) feats = (const float*)d_in[i];
        else if (in_sizes[i] == KK * KK)      trans = (const float*)d_in[i];
        else if (in_sizes[i] == BB * TT)      masks = d_in[i];
    }
    if (!feats || !trans || !masks) return;

    float* out   = (float*)d_out;
    float* score = nullptr;
    float* dec   = nullptr;
    if (out_size == BB * TT + BB) { score = out; dec = out + BB; }   // (path_score, decode)
    else if (out_size == BB * TT) { dec = out; }
    else if (out_size == BB)      { score = out; }
    else                          { score = out; if (out_size >= BB * TT + BB) dec = out + BB; }

    int smem_bytes = 65536 + 8 * TT * KK + 8 * 2176;   // trans + bp + staging = 214016
    cudaFuncSetAttribute(viterbi_kernel, cudaFuncAttributeMaxDynamicSharedMemorySize, smem_bytes);
    viterbi_kernel<<<BB / 8, 256, smem_bytes>>>(feats, trans, masks, score, dec);
}

// round 11
// speedup vs baseline: 1.0374x; 1.0374x over previous
#include <cuda_runtime.h>

#define BB 1024
#define TT 128
#define KK 128
#define START_TAG 126
#define STOP_TAG 127
#define NREC 140               // record slots per buffer: 0..135 data/pads, 136 dump
#define DUMP_SLOT 136
#define CLRX 0xFF7FFFFFu       // -FLT_MAX bits

// Per-warp length from the monotone mask row. Mask dtype detected from first word.
__device__ __forceinline__ int warp_len(const void* masks, int b, int lane) {
    unsigned w0 = *(const unsigned*)masks;
    int cnt;
    if (w0 == 0x01010101u) {
        unsigned v = ((const unsigned*)((const char*)masks + (size_t)b * TT))[lane];
        cnt = __popc(v & 0x01010101u);
    } else if (w0 == 0x3F800000u) {
        float4 v = ((const float4*)((const float*)masks + (size_t)b * TT))[lane];
        cnt = (v.x != 0.0f) + (v.y != 0.0f) + (v.z != 0.0f) + (v.w != 0.0f);
    } else {
        int4 v = ((const int4*)((const int*)masks + (size_t)b * TT))[lane];
        cnt = (v.x != 0) + (v.y != 0) + (v.z != 0) + (v.w != 0);
    }
    return __reduce_add_sync(0xffffffffu, cnt);
}

// ---------------------------------------------------------------------------
// Fused Viterbi: warp per batch, lane owns cur/prev = {4*lane .. 4*lane+3}.
// Straight-line forward (127 steps every warp, predicated t==last snapshot).
// Branch-free compaction (dump-slot stores); candidate consumption via a
// fallthrough switch on pair count: only ceil(ncand/2) record-pairs execute.
// Descending scan with >= == ascending scan with > (first-index ties kept).
// SMEM: 64KB trans + 8x16KB bp + 8x2240B staging -> 1 CTA/SM.
// ---------------------------------------------------------------------------
extern "C" __global__ void __launch_bounds__(256, 1)
viterbi_kernel(const float* __restrict__ feats,
               const float* __restrict__ trans,
               const void*  __restrict__ masks,
               float* __restrict__ out_score,
               float* __restrict__ out_dec) {
    extern __shared__ char smem[];
    float* ts = (float*)smem;                      // [prev*128 + cur], 64 KB
    __shared__ float s_wr[4];
    __shared__ float s_delta;

    int tid = threadIdx.x;

    for (int i = tid; i < KK * KK / 4; i += 256)
        ((float4*)ts)[i] = ((const float4*)trans)[i];
    __syncthreads();

    // Exact prune bound: Delta = max over cur of (max-min of trans[:,cur]) + margin
    if (tid < 128) {
        float mx = -3.4e38f, mn = 3.4e38f;
        #pragma unroll 8
        for (int p = 0; p < 128; p++) {
            float v = ts[p * 128 + tid];
            mx = fmaxf(mx, v); mn = fminf(mn, v);
        }
        float r = mx - mn;
        #pragma unroll
        for (int o = 16; o; o >>= 1) r = fmaxf(r, __shfl_xor_sync(0xffffffffu, r, o));
        if ((tid & 31) == 0) s_wr[tid >> 5] = r;
    }
    __syncthreads();
    if (tid == 0)
        s_delta = fmaxf(fmaxf(s_wr[0], s_wr[1]), fmaxf(s_wr[2], s_wr[3])) + 1e-3f;
    __syncthreads();
    float delta = s_delta;

    int w = tid >> 5, lane = tid & 31;
    int b = blockIdx.x * 8 + w;
    unsigned char* bp = (unsigned char*)(smem + 65536 + w * (TT * KK));            // 16 KB/warp
    uint2* cand = (uint2*)(smem + 65536 + 8 * TT * KK + w * (2 * NREC * 8));       // 2 bufs
    const float4* ts4 = (const float4*)ts;
    int last = warp_len(masks, b, lane) - 1;       // last >= 63

    const float4* fb4 = (const float4*)(feats + (size_t)b * TT * KK);  // 32 float4/row

    // t = 0: partition = feats[:,0,:] + trans[START,:]
    float4 f0  = fb4[lane];
    float4 tr0 = ((const float4*)(ts + START_TAG * KK))[lane];
    float v0 = f0.x + tr0.x, v1 = f0.y + tr0.y, v2 = f0.z + tr0.z, v3 = f0.w + tr0.w;
    float sv0 = v0, sv1 = v1, sv2 = v2, sv3 = v3;  // snapshot at t == last

    unsigned lmask = (1u << lane) - 1u;
    int p0 = lane * 4;
    int padlane = (lane < 3) ? lane : 2;           // 3 pad slots (dup lanes merge)

    // one Viterbi step
    auto step = [&](int t, float4 fc) {
        // warp max via +64 bias (partitions > -12 -> positive -> uint-monotone)
        float lm = fmaxf(fmaxf(v0, v1), fmaxf(v2, v3));
        unsigned mu = __reduce_max_sync(0xffffffffu, __float_as_uint(lm + 64.0f));
        unsigned u0 = __float_as_uint((v0 + delta) + 64.0f);
        unsigned u1 = __float_as_uint((v1 + delta) + 64.0f);
        unsigned u2 = __float_as_uint((v2 + delta) + 64.0f);
        unsigned u3 = __float_as_uint((v3 + delta) + 64.0f);

        unsigned c0 = __ballot_sync(0xffffffffu, u0 >= mu);
        unsigned c1 = __ballot_sync(0xffffffffu, u1 >= mu);
        unsigned c2 = __ballot_sync(0xffffffffu, u2 >= mu);
        unsigned c3 = __ballot_sync(0xffffffffu, u3 >= mu);
        int n0 = __popc(c0), n01 = n0 + __popc(c1), n012 = n01 + __popc(c2);
        int ncand = n012 + __popc(c3);

        // branch-free compaction: unconditional stores, losers to dump slot
        // (comp-major order: prev = 0,4,..,124, then 1,5,.., ...)
        uint2* cb = cand + ((t & 1) ? NREC : 0);
        int s0i = ((c0 >> lane) & 1u) ?          __popc(c0 & lmask) : DUMP_SLOT;
        int s1i = ((c1 >> lane) & 1u) ? n0   +   __popc(c1 & lmask) : DUMP_SLOT;
        int s2i = ((c2 >> lane) & 1u) ? n01  +   __popc(c2 & lmask) : DUMP_SLOT;
        int s3i = ((c3 >> lane) & 1u) ? n012 +   __popc(c3 & lmask) : DUMP_SLOT;
        cb[s0i] = make_uint2(__float_as_uint(v0), p0 + 0);
        cb[s1i] = make_uint2(__float_as_uint(v1), p0 + 1);
        cb[s2i] = make_uint2(__float_as_uint(v2), p0 + 2);
        cb[s3i] = make_uint2(__float_as_uint(v3), p0 + 3);
        cb[ncand + padlane] = make_uint2(CLRX, 0);          // -FLT_MAX pads
        __syncwarp();

        // consume records DESCENDING with >= : identical winner (lowest index on
        // exact ties) as ascending with >. Only ceil(ncand/2) pairs execute.
        float b0 = -3.4e38f, b1 = -3.4e38f, b2 = -3.4e38f, b3 = -3.4e38f;
        int   i0 = 0, i1 = 0, i2 = 0, i3 = 0;
        const uint4* cb4 = (const uint4*)cb;

        #define PROCGE(PVU, PREV)                                                    \
        {   float pv = __uint_as_float(PVU); int prev = (int)(PREV);                 \
            float4 tr = ts4[prev * 32 + lane];                                       \
            float qa = (pv + tr.x) + fc.x; if (qa >= b0) { b0 = qa; i0 = prev; }     \
            float qb = (pv + tr.y) + fc.y; if (qb >= b1) { b1 = qb; i1 = prev; }     \
            float qc = (pv + tr.z) + fc.z; if (qc >= b2) { b2 = qc; i2 = prev; }     \
            float qd = (pv + tr.w) + fc.w; if (qd >= b3) { b3 = qd; i3 = prev; }     \
        }
        #define PAIR(G)                                                              \
        {   uint4 rr = cb4[G];                                                       \
            PROCGE(rr.z, rr.w)      /* record 2G+1 (higher index) first */           \
            PROCGE(rr.x, rr.y)                                                       \
        }
        int np = (ncand + 1) >> 1;                 // pair count, >= 1
        if (np > 4) {                              // warp-uniform, uncommon
            for (int g = np - 1; g >= 4; --g) PAIR(g)
            np = 4;
        }
        switch (np) {
            case 4: PAIR(3) [[fallthrough]];
            case 3: PAIR(2) [[fallthrough]];
            case 2: PAIR(1) [[fallthrough]];
            default: PAIR(0)
        }
        #undef PAIR
        #undef PROCGE

        // packed backpointers: byte for cur=c at bp[t*128 + c]
        ((unsigned*)(bp + t * KK))[lane] =
            (unsigned)i0 | ((unsigned)i1 << 8) | ((unsigned)i2 << 16) | ((unsigned)i3 << 24);

        v0 = b0; v1 = b1; v2 = b2; v3 = b3;
        bool atlast = (t == last);                 // predicated snapshot (off-chain)
        sv0 = atlast ? v0 : sv0; sv1 = atlast ? v1 : sv1;
        sv2 = atlast ? v2 : sv2; sv3 = atlast ? v3 : sv3;
    };

    // feat register ring, depth 4; refill clamped to row 127 (dup row, never consumed)
    float4 r0 = fb4[1 * 32 + lane], r1 = fb4[2 * 32 + lane];
    float4 r2 = fb4[3 * 32 + lane], r3 = fb4[4 * 32 + lane];

    #pragma unroll 1
    for (int tb = 1; tb <= 121; tb += 4) {
        int a4 = min(tb + 4, 127) * 32 + lane, a5 = min(tb + 5, 127) * 32 + lane;
        int a6 = min(tb + 6, 127) * 32 + lane, a7 = min(tb + 7, 127) * 32 + lane;
        float4 fa = r0;  r0 = fb4[a4]; step(tb + 0, fa);
        float4 fb_ = r1; r1 = fb4[a5]; step(tb + 1, fb_);
        float4 fcx = r2; r2 = fb4[a6]; step(tb + 2, fcx);
        float4 fd = r3;  r3 = fb4[a7]; step(tb + 3, fd);
    }
    step(125, r0); step(126, r1); step(127, r2);   // peeled tail (t = 1..127 total)

    // STOP transition argmax from snapshot (first-index ties)
    float q0 = sv0 + ts[(p0 + 0) * KK + STOP_TAG];
    float q1 = sv1 + ts[(p0 + 1) * KK + STOP_TAG];
    float q2 = sv2 + ts[(p0 + 2) * KK + STOP_TAG];
    float q3 = sv3 + ts[(p0 + 3) * KK + STOP_TAG];
    float bv = q0; int bi = p0;
    if (q1 > bv) { bv = q1; bi = p0 + 1; }
    if (q2 > bv) { bv = q2; bi = p0 + 2; }
    if (q3 > bv) { bv = q3; bi = p0 + 3; }
    #pragma unroll
    for (int o = 16; o; o >>= 1) {
        float ov = __shfl_xor_sync(0xffffffffu, bv, o);
        int   oi = __shfl_xor_sync(0xffffffffu, bi, o);
        if (ov > bv || (ov == bv && oi < bi)) { bv = ov; bi = oi; }
    }
    int cur = bi;   // warp-uniform

    if (out_score && lane == 0) out_score[b] = bv;

    if (out_dec) {
        float* od = out_dec + (size_t)b * TT;
        for (int t = last + 1 + lane; t < TT - 1; t += 32) od[t] = 0.0f;   // masked tail
        if (lane == 0) { od[TT - 1] = (float)cur; od[last] = (float)cur; } // ref quirk
        for (int t = last; t >= 1; t--) {
            cur = bp[t * KK + cur];                 // uniform SMEM pointer chase
            if (lane == 0) od[t - 1] = (float)cur;
        }
    }
}

// ---------------------------------------------------------------------------
extern "C" void kernel_launch(void* const* d_in, const int* in_sizes, int n_in,
                              void* d_out, int out_size) {
    const float* feats = nullptr;
    const float* trans = nullptr;
    const void*  masks = nullptr;
    for (int i = 0; i < n_in; i++) {
        if      (in_sizes[i] == BB * TT * KK) feats = (const float*)d_in[i];
        else if (in_sizes[i] == KK * KK)      trans = (const float*)d_in[i];
        else if (in_sizes[i] == BB * TT)      masks = d_in[i];
    }
    if (!feats || !trans || !masks) return;

    float* out   = (float*)d_out;
    float* score = nullptr;
    float* dec   = nullptr;
    if (out_size == BB * TT + BB) { score = out; dec = out + BB; }   // (path_score, decode)
    else if (out_size == BB * TT) { dec = out; }
    else if (out_size == BB)      { score = out; }
    else                          { score = out; if (out_size >= BB * TT + BB) dec = out + BB; }

    int smem_bytes = 65536 + 8 * TT * KK + 8 * (2 * NREC * 8);   // 214528
    cudaFuncSetAttribute(viterbi_kernel, cudaFuncAttributeMaxDynamicSharedMemorySize, smem_bytes);
    viterbi_kernel<<<BB / 8, 256, smem_bytes>>>(feats, trans, masks, score, dec);
}

// round 12
// speedup vs baseline: 1.2828x; 1.2366x over previous
#include <cuda_runtime.h>

#define BB 1024
#define TT 128
#define KK 128
#define START_TAG 126
#define STOP_TAG 127
#define WPC 7                  // warps (batches) per CTA
#define NREC 140               // record slots per buffer: 0..135 data/pads, 136 dump
#define DUMP_SLOT 136
#define CLRX 0xFF7FFFFFu       // -FLT_MAX bits

// Per-warp length from the monotone mask row. Mask dtype detected from first word.
__device__ __forceinline__ int warp_len(const void* masks, int b, int lane) {
    unsigned w0 = *(const unsigned*)masks;
    int cnt;
    if (w0 == 0x01010101u) {
        unsigned v = ((const unsigned*)((const char*)masks + (size_t)b * TT))[lane];
        cnt = __popc(v & 0x01010101u);
    } else if (w0 == 0x3F800000u) {
        float4 v = ((const float4*)((const float*)masks + (size_t)b * TT))[lane];
        cnt = (v.x != 0.0f) + (v.y != 0.0f) + (v.z != 0.0f) + (v.w != 0.0f);
    } else {
        int4 v = ((const int4*)((const int*)masks + (size_t)b * TT))[lane];
        cnt = (v.x != 0) + (v.y != 0) + (v.z != 0) + (v.w != 0);
    }
    return __reduce_add_sync(0xffffffffu, cnt);
}

// ---------------------------------------------------------------------------
// Fused Viterbi: warp per batch, lane owns cur/prev = {4*lane .. 4*lane+3}.
// R9 step body (proven 67.6us / rel_err 0.0) with contention-reducing
// geometry: 7 warps/CTA over 147 CTAs (spreads smem-crossbar + issue load
// across more SMs) and block-granular (every 4 steps) early exit.
// SMEM: 64KB trans + 7x16KB bp + 7x2240B staging = ~191KB -> 1 CTA/SM.
// ---------------------------------------------------------------------------
extern "C" __global__ void __launch_bounds__(224, 1)
viterbi_kernel(const float* __restrict__ feats,
               const float* __restrict__ trans,
               const void*  __restrict__ masks,
               float* __restrict__ out_score,
               float* __restrict__ out_dec) {
    extern __shared__ char smem[];
    float* ts = (float*)smem;                      // [prev*128 + cur], 64 KB
    __shared__ float s_wr[4];
    __shared__ float s_delta;

    int tid = threadIdx.x;

    for (int i = tid; i < KK * KK / 4; i += 224)
        ((float4*)ts)[i] = ((const float4*)trans)[i];
    __syncthreads();

    // Exact prune bound: Delta = max over cur of (max-min of trans[:,cur]) + margin
    if (tid < 128) {
        float mx = -3.4e38f, mn = 3.4e38f;
        #pragma unroll 8
        for (int p = 0; p < 128; p++) {
            float v = ts[p * 128 + tid];
            mx = fmaxf(mx, v); mn = fminf(mn, v);
        }
        float r = mx - mn;
        #pragma unroll
        for (int o = 16; o; o >>= 1) r = fmaxf(r, __shfl_xor_sync(0xffffffffu, r, o));
        if ((tid & 31) == 0) s_wr[tid >> 5] = r;
    }
    __syncthreads();
    if (tid == 0)
        s_delta = fmaxf(fmaxf(s_wr[0], s_wr[1]), fmaxf(s_wr[2], s_wr[3])) + 1e-3f;
    __syncthreads();
    float delta = s_delta;

    int w = tid >> 5, lane = tid & 31;
    int b = blockIdx.x * WPC + w;
    bool valid = (b < BB);
    int bl = valid ? b : (BB - 1);                 // clamped batch for loads
    unsigned char* bp = (unsigned char*)(smem + 65536 + w * (TT * KK));            // 16 KB/warp
    uint2* cand = (uint2*)(smem + 65536 + WPC * TT * KK + w * (2 * NREC * 8));     // 2 bufs
    const float4* ts4 = (const float4*)ts;
    int last = warp_len(masks, bl, lane) - 1;      // last >= 63

    const float4* fb4 = (const float4*)(feats + (size_t)bl * TT * KK);  // 32 float4/row

    // t = 0: partition = feats[:,0,:] + trans[START,:]
    float4 f0  = fb4[lane];
    float4 tr0 = ((const float4*)(ts + START_TAG * KK))[lane];
    float v0 = f0.x + tr0.x, v1 = f0.y + tr0.y, v2 = f0.z + tr0.z, v3 = f0.w + tr0.w;
    float sv0 = v0, sv1 = v1, sv2 = v2, sv3 = v3;  // snapshot at t == last

    unsigned lmask = (1u << lane) - 1u;
    int p0 = lane * 4;
    int padlane = (lane < 7) ? lane : 6;           // pad slot offset (dup lanes merge)

    // one Viterbi step (R9 body: branch-free compaction + 8-record tree)
    auto step = [&](int t, float4 fc) {
        // Warp max via +64 bias (partitions > -12 -> positive -> uint-monotone).
        float lm = fmaxf(fmaxf(v0, v1), fmaxf(v2, v3));
        unsigned mu = __reduce_max_sync(0xffffffffu, __float_as_uint(lm + 64.0f));
        unsigned u0 = __float_as_uint((v0 + delta) + 64.0f);
        unsigned u1 = __float_as_uint((v1 + delta) + 64.0f);
        unsigned u2 = __float_as_uint((v2 + delta) + 64.0f);
        unsigned u3 = __float_as_uint((v3 + delta) + 64.0f);

        unsigned c0 = __ballot_sync(0xffffffffu, u0 >= mu);
        unsigned c1 = __ballot_sync(0xffffffffu, u1 >= mu);
        unsigned c2 = __ballot_sync(0xffffffffu, u2 >= mu);
        unsigned c3 = __ballot_sync(0xffffffffu, u3 >= mu);
        int n0 = __popc(c0), n01 = n0 + __popc(c1), n012 = n01 + __popc(c2);
        int ncand = n012 + __popc(c3);

        // BRANCH-FREE compaction: unconditional stores, losers go to dump slot.
        // comp-major order (prev = 0,4,..,124, then 1,5,..) — same as prior rounds.
        uint2* cb = cand + ((t & 1) ? NREC : 0);
        int s0i = ((c0 >> lane) & 1u) ?          __popc(c0 & lmask) : DUMP_SLOT;
        int s1i = ((c1 >> lane) & 1u) ? n0   +   __popc(c1 & lmask) : DUMP_SLOT;
        int s2i = ((c2 >> lane) & 1u) ? n01  +   __popc(c2 & lmask) : DUMP_SLOT;
        int s3i = ((c3 >> lane) & 1u) ? n012 +   __popc(c3 & lmask) : DUMP_SLOT;
        cb[s0i] = make_uint2(__float_as_uint(v0), p0 + 0);
        cb[s1i] = make_uint2(__float_as_uint(v1), p0 + 1);
        cb[s2i] = make_uint2(__float_as_uint(v2), p0 + 2);
        cb[s3i] = make_uint2(__float_as_uint(v3), p0 + 3);
        cb[ncand + padlane] = make_uint2(CLRX, 0);   // -FLT_MAX pads (unconditional)
        __syncwarp();

        // fast path: records 0-7, q computed in parallel then depth-3 tree max
        // (left-preference >= on ties == first-in-scan-order winner)
        const uint4* cb4 = (const uint4*)cb;
        uint4 ra = cb4[0], rb = cb4[1], rc = cb4[2], rd = cb4[3];
        float q0[8], q1[8], q2[8], q3[8]; int pi[8];
        #define LOADREC(K, PVU, PREV)                                                \
        {   float pv = __uint_as_float(PVU); int prev = (int)(PREV); pi[K] = prev;   \
            float4 tr = ts4[prev * 32 + lane];                                       \
            q0[K] = (pv + tr.x) + fc.x; q1[K] = (pv + tr.y) + fc.y;                  \
            q2[K] = (pv + tr.z) + fc.z; q3[K] = (pv + tr.w) + fc.w;                  \
        }
        LOADREC(0, ra.x, ra.y) LOADREC(1, ra.z, ra.w)
        LOADREC(2, rb.x, rb.y) LOADREC(3, rb.z, rb.w)
        LOADREC(4, rc.x, rc.y) LOADREC(5, rc.z, rc.w)
        LOADREC(6, rd.x, rd.y) LOADREC(7, rd.z, rd.w)
        #undef LOADREC

        float b0, b1, b2, b3; int i0, i1, i2, i3;
        #define TREE(Q, BO, IO)                                                      \
        {   bool c01 = Q[0] >= Q[1], c23 = Q[2] >= Q[3];                             \
            bool c45 = Q[4] >= Q[5], c67 = Q[6] >= Q[7];                             \
            float m01 = c01 ? Q[0] : Q[1]; int j01 = c01 ? pi[0] : pi[1];            \
            float m23 = c23 ? Q[2] : Q[3]; int j23 = c23 ? pi[2] : pi[3];            \
            float m45 = c45 ? Q[4] : Q[5]; int j45 = c45 ? pi[4] : pi[5];            \
            float m67 = c67 ? Q[6] : Q[7]; int j67 = c67 ? pi[6] : pi[7];            \
            bool ca = m01 >= m23, cbp = m45 >= m67;                                  \
            float ma = ca ? m01 : m23; int ja = ca ? j01 : j23;                      \
            float mb = cbp ? m45 : m67; int jb = cbp ? j45 : j67;                    \
            bool cf = ma >= mb;                                                      \
            BO = cf ? ma : mb; IO = cf ? ja : jb;                                    \
        }
        TREE(q0, b0, i0) TREE(q1, b1, i1) TREE(q2, b2, i2) TREE(q3, b3, i3)
        #undef TREE

        if (ncand > 8) {                            // warp-uniform, uncommon
            int ng = (ncand + 3) >> 2;
            for (int g = 2; g < ng; g++) {
                uint4 rx = cb4[2 * g], ry = cb4[2 * g + 1];
                #define PROC(PVU, PREV)                                                  \
                {   float pv = __uint_as_float(PVU); int prev = (int)(PREV);             \
                    float4 tr = ts4[prev * 32 + lane];                                   \
                    float qa = (pv + tr.x) + fc.x; if (qa > b0) { b0 = qa; i0 = prev; }  \
                    float qb = (pv + tr.y) + fc.y; if (qb > b1) { b1 = qb; i1 = prev; }  \
                    float qc = (pv + tr.z) + fc.z; if (qc > b2) { b2 = qc; i2 = prev; }  \
                    float qd = (pv + tr.w) + fc.w; if (qd > b3) { b3 = qd; i3 = prev; }  \
                }
                PROC(rx.x, rx.y) PROC(rx.z, rx.w) PROC(ry.x, ry.y) PROC(ry.z, ry.w)
                #undef PROC
            }
        }

        // packed backpointers: byte for cur=c at bp[t*128 + c]
        ((unsigned*)(bp + t * KK))[lane] =
            (unsigned)i0 | ((unsigned)i1 << 8) | ((unsigned)i2 << 16) | ((unsigned)i3 << 24);

        v0 = b0; v1 = b1; v2 = b2; v3 = b3;
        bool atlast = (t == last);                  // predicated snapshot (off-chain)
        sv0 = atlast ? v0 : sv0; sv1 = atlast ? v1 : sv1;
        sv2 = atlast ? v2 : sv2; sv3 = atlast ? v3 : sv3;
    };

    // feat register ring, depth 4; refill clamped to row 127 (dup row, never consumed)
    float4 r0 = fb4[1 * 32 + lane], r1 = fb4[2 * 32 + lane];
    float4 r2 = fb4[3 * 32 + lane], r3 = fb4[4 * 32 + lane];

    #pragma unroll 1
    for (int tb = 1; tb <= 121; tb += 4) {
        if (tb > last) break;                      // warp-uniform, once per 4 steps
        int a4 = min(tb + 4, 127) * 32 + lane, a5 = min(tb + 5, 127) * 32 + lane;
        int a6 = min(tb + 6, 127) * 32 + lane, a7 = min(tb + 7, 127) * 32 + lane;
        float4 fa = r0;  r0 = fb4[a4]; step(tb + 0, fa);
        float4 fb_ = r1; r1 = fb4[a5]; step(tb + 1, fb_);
        float4 fcx = r2; r2 = fb4[a6]; step(tb + 2, fcx);
        float4 fd = r3;  r3 = fb4[a7]; step(tb + 3, fd);
    }
    if (last >= 125) step(125, r0);                // peeled tail (warp-uniform guards)
    if (last >= 126) step(126, r1);
    if (last >= 127) step(127, r2);

    // STOP transition argmax from snapshot (first-index ties)
    float q0 = sv0 + ts[(p0 + 0) * KK + STOP_TAG];
    float q1 = sv1 + ts[(p0 + 1) * KK + STOP_TAG];
    float q2 = sv2 + ts[(p0 + 2) * KK + STOP_TAG];
    float q3 = sv3 + ts[(p0 + 3) * KK + STOP_TAG];
    float bv = q0; int bi = p0;
    if (q1 > bv) { bv = q1; bi = p0 + 1; }
    if (q2 > bv) { bv = q2; bi = p0 + 2; }
    if (q3 > bv) { bv = q3; bi = p0 + 3; }
    #pragma unroll
    for (int o = 16; o; o >>= 1) {
        float ov = __shfl_xor_sync(0xffffffffu, bv, o);
        int   oi = __shfl_xor_sync(0xffffffffu, bi, o);
        if (ov > bv || (ov == bv && oi < bi)) { bv = ov; bi = oi; }
    }
    int cur = bi;   // warp-uniform

    if (valid && out_score && lane == 0) out_score[b] = bv;

    if (valid && out_dec) {
        float* od = out_dec + (size_t)b * TT;
        for (int t = last + 1 + lane; t < TT - 1; t += 32) od[t] = 0.0f;   // masked tail
        if (lane == 0) { od[TT - 1] = (float)cur; od[last] = (float)cur; } // ref quirk
        for (int t = last; t >= 1; t--) {
            cur = bp[t * KK + cur];                 // uniform SMEM pointer chase
            if (lane == 0) od[t - 1] = (float)cur;
        }
    }
}

// ---------------------------------------------------------------------------
extern "C" void kernel_launch(void* const* d_in, const int* in_sizes, int n_in,
                              void* d_out, int out_size) {
    const float* feats = nullptr;
    const float* trans = nullptr;
    const void*  masks = nullptr;
    for (int i = 0; i < n_in; i++) {
        if      (in_sizes[i] == BB * TT * KK) feats = (const float*)d_in[i];
        else if (in_sizes[i] == KK * KK)      trans = (const float*)d_in[i];
        else if (in_sizes[i] == BB * TT)      masks = d_in[i];
    }
    if (!feats || !trans || !masks) return;

    float* out   = (float*)d_out;
    float* score = nullptr;
    float* dec   = nullptr;
    if (out_size == BB * TT + BB) { score = out; dec = out + BB; }   // (path_score, decode)
    else if (out_size == BB * TT) { dec = out; }
    else if (out_size == BB)      { score = out; }
    else                          { score = out; if (out_size >= BB * TT + BB) dec = out + BB; }

    int grid = (BB + WPC - 1) / WPC;               // 147 CTAs
    int smem_bytes = 65536 + WPC * TT * KK + WPC * (2 * NREC * 8);   // 195856 -> pad
    cudaFuncSetAttribute(viterbi_kernel, cudaFuncAttributeMaxDynamicSharedMemorySize, smem_bytes);
    viterbi_kernel<<<grid, 224, smem_bytes>>>(feats, trans, masks, score, dec);
}